// round 13
// baseline (speedup 1.0000x reference)
#include <cuda_runtime.h>
#include <cuda_fp16.h>
#include <cstddef>
#include <cstdint>

#define B    16
#define NT   64
#define LN   256
#define LV   4
#define DIM  256
#define VOC  32000
#define MM   128
#define LS   4

// ---------------- scratch (device globals; no allocation) ----------------
__device__ __align__(16) float g_roots[B*NT*DIM];   // 1 MB
__device__ __align__(16) float g_x512[B*2*DIM];     // [u | o0] per b
__device__ __align__(16) float g_M   [4*B*MM*DIM];  // 8 MB: sum_s C[k][story]
__device__ __align__(16) float g_gi  [B*3*DIM];
__device__ __align__(16) float g_gh  [B*3*DIM];
__device__ __align__(16) float g_q   [B*DIM];
__device__ __align__(16) __half g_C0h[VOC*DIM];     // 16.4 MB fp16 C0
__device__ __align__(16) __half g_W1h[(size_t)VOC*2*DIM]; // 32.8 MB fp16 W1w [v][j]

__device__ __forceinline__ float warp_sum(float v) {
    #pragma unroll
    for (int o = 16; o; o >>= 1) v += __shfl_xor_sync(0xffffffffu, v, o);
    return v;
}
__device__ __forceinline__ float warp_max(float v) {
    #pragma unroll
    for (int o = 16; o; o >>= 1) v = fmaxf(v, __shfl_xor_sync(0xffffffffu, v, o));
    return v;
}
__device__ __forceinline__ void prefetch_l2(const void* p) {
    asm volatile("prefetch.global.L2 [%0];" :: "l"(p));
}
__device__ __forceinline__ unsigned int smem_u32(const void* p) {
    unsigned int a;
    asm("{ .reg .u64 t; cvta.to.shared.u64 t, %1; cvt.u32.u64 %0, t; }"
        : "=r"(a) : "l"(p));
    return a;
}
__device__ __forceinline__ void cp_async8(unsigned int dst, const void* src) {
    asm volatile("cp.async.ca.shared.global [%0], [%1], 8;" :: "r"(dst), "l"(src));
}
__device__ __forceinline__ void cp_commit() {
    asm volatile("cp.async.commit_group;" ::: "memory");
}

// f32x2 packed helpers (Blackwell dual-FMA pipe)
__device__ __forceinline__ unsigned long long pack2(float a, float b) {
    unsigned long long r;
    asm("mov.b64 %0, {%1, %2};" : "=l"(r) : "f"(a), "f"(b));
    return r;
}
__device__ __forceinline__ void fma2(unsigned long long& d, unsigned long long a, unsigned long long b) {
    asm("fma.rn.f32x2 %0, %1, %2, %0;" : "+l"(d) : "l"(a), "l"(b));
}
__device__ __forceinline__ void unpack2(unsigned long long v, float& lo, float& hi) {
    asm("mov.b64 {%0, %1}, %2;" : "=f"(lo), "=f"(hi) : "l"(v));
}

// ================= K0: convert C0 -> fp16 =================
__global__ __launch_bounds__(256) void K0(const float* __restrict__ C)
{
    size_t i = (size_t)blockIdx.x * 256 + threadIdx.x;
    const float4* C4 = (const float4*)C;
    float4 v = __ldcg(&C4[i]);
    union { __half2 h[2]; uint2 u; } cv;
    cv.h[0] = __floats2half2_rn(v.x, v.y);
    cv.h[1] = __floats2half2_rn(v.z, v.w);
    *(uint2*)&g_C0h[i*4] = cv.u;
}

// ================= K1: fused front-end (+ W1w fp16 convert) ===============
#define K1_ROOTS  1024
#define K1_STORY  512
#define K1_GEMV   128
#define K1_WCONV  256
__global__ __launch_bounds__(256) void K1(
    const int* __restrict__ kb_values, const int* __restrict__ kb_types,
    const float* __restrict__ C, const float* __restrict__ T_emb,
    const int* __restrict__ story,
    const int* __restrict__ dec, const float* __restrict__ hidden,
    const float* __restrict__ W_ih, const float* __restrict__ W_hh,
    const float* __restrict__ Wq,
    const float* __restrict__ b_ih, const float* __restrict__ b_hh,
    const float* __restrict__ W1w)
{
    __shared__ union {
        struct { int vals[LN*LV]; int types[LN]; float4 part[3*64]; } rb;
        struct { float x[DIM]; float h[DIM]; } gv;
    } sh;

    int blk = blockIdx.x;
    int t   = threadIdx.x;

    if (blk < K1_ROOTS) {
        int bn = blk;
        int g  = t >> 6;
        int c  = t & 63;
        const int* vp = kb_values + (size_t)bn * LN * LV;
        for (int i = t; i < LN*LV; i += 256) sh.rb.vals[i] = vp[i];
        sh.rb.types[t] = kb_types[(size_t)bn*LN + t];
        __syncthreads();

        const uint2* C0h = (const uint2*)g_C0h;
        const float4* TE = (const float4*)T_emb;
        float4 acc = make_float4(0.f,0.f,0.f,0.f);
        #pragma unroll 4
        for (int l = g; l < LN; l += 4) {
            int4 vv = *(const int4*)&sh.rb.vals[l*4];
            int  ty = sh.rb.types[l];
            float4 te = TE[(size_t)ty*64 + c];
            uint2 r0 = __ldcg(&C0h[(size_t)vv.x*64 + c]);
            uint2 r1 = __ldcg(&C0h[(size_t)vv.y*64 + c]);
            uint2 r2 = __ldcg(&C0h[(size_t)vv.z*64 + c]);
            uint2 r3 = __ldcg(&C0h[(size_t)vv.w*64 + c]);
            __half2 s01 = __hadd2(__hadd2(*(__half2*)&r0.x, *(__half2*)&r1.x),
                                  __hadd2(*(__half2*)&r2.x, *(__half2*)&r3.x));
            __half2 s23 = __hadd2(__hadd2(*(__half2*)&r0.y, *(__half2*)&r1.y),
                                  __hadd2(*(__half2*)&r2.y, *(__half2*)&r3.y));
            float2 f01 = __half22float2(s01);
            float2 f23 = __half22float2(s23);
            acc.x += te.x * f01.x;
            acc.y += te.y * f01.y;
            acc.z += te.z * f23.x;
            acc.w += te.w * f23.y;
        }
        if (g) sh.rb.part[(g-1)*64 + c] = acc;
        __syncthreads();
        if (!g) {
            float4 p0 = sh.rb.part[c], p1 = sh.rb.part[64+c], p2 = sh.rb.part[128+c];
            acc.x += p0.x+p1.x+p2.x;  acc.y += p0.y+p1.y+p2.y;
            acc.z += p0.z+p1.z+p2.z;  acc.w += p0.w+p1.w+p2.w;
            *(float4*)&g_roots[((size_t)bn*64 + c)*4] = acc;
        }
    } else if (blk < K1_ROOTS + K1_STORY) {
        int bm = (blk - K1_ROOTS)*4 + (t >> 6);
        int c  = t & 63;
        const int* st = story + (size_t)bm*LS;
        int i0 = st[0], i1 = st[1], i2 = st[2], i3 = st[3];
        const float4* Cf = (const float4*)C;
        float4* Mf = (float4*)g_M;
        #pragma unroll
        for (int k = 0; k < 4; k++) {
            const float4* Ck = Cf + (size_t)k * VOC * 64;
            float4 a  = __ldcg(&Ck[(size_t)i0*64 + c]);
            float4 b4 = __ldcg(&Ck[(size_t)i1*64 + c]);
            float4 c4 = __ldcg(&Ck[(size_t)i2*64 + c]);
            float4 d4 = __ldcg(&Ck[(size_t)i3*64 + c]);
            float4 r;
            r.x=(a.x+b4.x)+(c4.x+d4.x); r.y=(a.y+b4.y)+(c4.y+d4.y);
            r.z=(a.z+b4.z)+(c4.z+d4.z); r.w=(a.w+b4.w)+(c4.w+d4.w);
            Mf[((size_t)k*B*MM + bm)*64 + c] = r;
        }
    } else if (blk < K1_ROOTS + K1_STORY + K1_GEMV) {
        int g2 = blk - (K1_ROOTS + K1_STORY);
        int b    = g2 >> 3;
        int part = g2 & 7;
        int w = t >> 5, lane = t & 31;

        if (t < DIM) {
            sh.gv.h[t] = hidden[b*DIM + t];
            sh.gv.x[t] = C[(size_t)dec[b]*DIM + t];
        }
        __syncthreads();
        const float4* x4 = (const float4*)sh.gv.x;
        const float4* h4 = (const float4*)sh.gv.h;

        int base = part*224;
        #pragma unroll 4
        for (int i = 0; i < 28; i++) {
            int o = base + w + 8*i;
            const float* Wrow;
            const float4* v;
            if (o < 768)        { Wrow = W_ih + (size_t)o*DIM;        v = x4; }
            else if (o < 1536)  { Wrow = W_hh + (size_t)(o-768)*DIM;  v = h4; }
            else                { Wrow = Wq   + (size_t)(o-1536)*DIM; v = h4; }
            const float4* W4 = (const float4*)Wrow;
            float4 wa = W4[lane],      va = v[lane];
            float4 wb = W4[lane + 32], vb = v[lane + 32];
            float s = wa.x*va.x + wa.y*va.y + wa.z*va.z + wa.w*va.w
                    + wb.x*vb.x + wb.y*vb.y + wb.z*vb.z + wb.w*vb.w;
            s = warp_sum(s);
            if (lane == 0) {
                if (o < 768)       g_gi[b*768 + o]        = s + b_ih[o];
                else if (o < 1536) g_gh[b*768 + (o-768)]  = s + b_hh[o-768];
                else               g_q [b*DIM + (o-1536)] = s;
            }
        }
    } else {
        // ---- W1w -> fp16 convert (runs under K1's LTS-bound phase) ----
        int pb = blk - (K1_ROOTS + K1_STORY + K1_GEMV);   // 0..255
        const float4* W4 = (const float4*)W1w;
        const size_t total = (size_t)VOC*512/4;            // 4,096,000 float4
        #pragma unroll 4
        for (int k = 0; k < 63; k++) {
            size_t i = (size_t)(pb*256 + t) + (size_t)k*65536;
            if (i < total) {
                float4 v = __ldcg(&W4[i]);
                union { __half2 h[2]; uint2 u; } cv;
                cv.h[0] = __floats2half2_rn(v.x, v.y);
                cv.h[1] = __floats2half2_rn(v.z, v.w);
                *(uint2*)&g_W1h[i*4] = cv.u;
            }
        }
    }
}

// ===== K234: kv+GRU+attention+3 hops, one block per b (1024 threads) ======
__global__ __launch_bounds__(1024) void K234(
    const float* __restrict__ Wk, const float* __restrict__ hidden,
    const float* __restrict__ Wv, float* __restrict__ out_hnew,
    float* __restrict__ out_pptr)
{
    int b = blockIdx.x, t = threadIdx.x;
    int w = t >> 5, lane = t & 31;
    int col = t & 255, q = t >> 8;
    __shared__ float s_q[DIM], s_kv[DIM], s_hn[DIM], s_sc[NT],
                     s_p[4*DIM], s_rbar[DIM], s_feat[DIM],
                     s_u[DIM], s_l[MM];
    __shared__ float s_inv;

    {
        const char* mb = (const char*)g_M;
        #pragma unroll
        for (int k = 0; k < 4; k++)
            prefetch_l2(mb + ((size_t)(k*B + b)*MM*DIM)*4 + (size_t)t*128);
    }

    if (t < DIM) s_q[t] = g_q[b*DIM + t];
    __syncthreads();

    {
        float p = 0.f;
        #pragma unroll 8
        for (int k = q*64; k < q*64 + 64; k++)
            p += Wk[(size_t)k*DIM + col] * s_q[k];
        s_p[q*DIM + col] = p;
    }
    __syncthreads();
    if (t < DIM) {
        s_kv[t] = (s_p[t] + s_p[DIM+t]) + (s_p[2*DIM+t] + s_p[3*DIM+t]);
        float gi0 = g_gi[b*768 + t],         gh0 = g_gh[b*768 + t];
        float gi1 = g_gi[b*768 + DIM + t],   gh1 = g_gh[b*768 + DIM + t];
        float gi2 = g_gi[b*768 + 2*DIM + t], gh2 = g_gh[b*768 + 2*DIM + t];
        float h   = hidden[b*DIM + t];
        float r  = 1.f / (1.f + __expf(-(gi0 + gh0)));
        float z  = 1.f / (1.f + __expf(-(gi1 + gh1)));
        float n  = tanhf(gi2 + r * gh2);
        float hn = (1.f - z) * n + z * h;
        s_hn[t] = hn;
        out_hnew[b*DIM + t] = hn;
    }
    __syncthreads();

    const float4* kv4 = (const float4*)s_kv;
    #pragma unroll
    for (int i = 0; i < 2; i++) {
        int n = w + 32*i;
        const float4* r4 = (const float4*)(g_roots + ((size_t)b*NT + n)*DIM);
        float4 ra = r4[lane], ka = kv4[lane];
        float4 rb = r4[lane+32], kb = kv4[lane+32];
        float sc = ra.x*ka.x + ra.y*ka.y + ra.z*ka.z + ra.w*ka.w
                 + rb.x*kb.x + rb.y*kb.y + rb.z*kb.z + rb.w*kb.w;
        float rs = (ra.x+ra.y+ra.z+ra.w) + (rb.x+rb.y+rb.z+rb.w);
        sc = warp_sum(sc);
        rs = warp_sum(rs);
        if (lane == 0) s_sc[n] = (rs == 0.0f) ? sc - 1e9f : sc;
    }
    __syncthreads();

    if (t < 32) {
        float a = fmaxf(s_sc[t], s_sc[t+32]);
        a = warp_max(a);
        float e0 = __expf(s_sc[t]-a), e1 = __expf(s_sc[t+32]-a);
        float inv = 1.f / warp_sum(e0 + e1);
        s_sc[t] = e0*inv; s_sc[t+32] = e1*inv;
    }
    __syncthreads();

    {
        float p = 0.f;
        #pragma unroll 8
        for (int n = q*16; n < q*16 + 16; n++)
            p += s_sc[n] * g_roots[((size_t)b*NT + n)*DIM + col];
        s_p[q*DIM + col] = p;
    }
    __syncthreads();
    if (t < DIM)
        s_rbar[t] = (s_p[t] + s_p[DIM+t]) + (s_p[2*DIM+t] + s_p[3*DIM+t]);
    __syncthreads();

    const float4* rb4 = (const float4*)s_rbar;
    #pragma unroll
    for (int i = 0; i < 8; i++) {
        int k = w + 32*i;
        const float4* W4 = (const float4*)(Wv + (size_t)k*DIM);
        float4 wa = W4[lane],    va = rb4[lane];
        float4 wb = W4[lane+32], vb = rb4[lane+32];
        float s = wa.x*va.x + wa.y*va.y + wa.z*va.z + wa.w*va.w
                + wb.x*vb.x + wb.y*vb.y + wb.z*vb.z + wb.w*vb.w;
        s = warp_sum(s);
        if (lane == 0) s_feat[k] = s;
    }
    __syncthreads();

    if (t < DIM) {
        float u = s_hn[t] + s_feat[t];
        s_u[t] = u;
        g_x512[b*2*DIM + t] = u;
    }
    __syncthreads();

    for (int hop = 0; hop < 3; hop++) {
        const float* MA = g_M + ((size_t)hop*B + b)*MM*DIM;
        const float4* u4 = (const float4*)s_u;
        {
            int m0 = w*4;
            float4 ua = u4[lane], ub = u4[lane+32];
            const float4* r0 = (const float4*)(MA + (size_t)(m0+0)*DIM);
            const float4* r1 = (const float4*)(MA + (size_t)(m0+1)*DIM);
            const float4* r2 = (const float4*)(MA + (size_t)(m0+2)*DIM);
            const float4* r3 = (const float4*)(MA + (size_t)(m0+3)*DIM);
            float4 v0 = r0[lane], v1 = r1[lane], v2 = r2[lane], v3 = r3[lane];
            float a0 = v0.x*ua.x + v0.y*ua.y + v0.z*ua.z + v0.w*ua.w;
            float a1 = v1.x*ua.x + v1.y*ua.y + v1.z*ua.z + v1.w*ua.w;
            float a2 = v2.x*ua.x + v2.y*ua.y + v2.z*ua.z + v2.w*ua.w;
            float a3 = v3.x*ua.x + v3.y*ua.y + v3.z*ua.z + v3.w*ua.w;
            v0 = r0[lane+32]; v1 = r1[lane+32]; v2 = r2[lane+32]; v3 = r3[lane+32];
            a0 += v0.x*ub.x + v0.y*ub.y + v0.z*ub.z + v0.w*ub.w;
            a1 += v1.x*ub.x + v1.y*ub.y + v1.z*ub.z + v1.w*ub.w;
            a2 += v2.x*ub.x + v2.y*ub.y + v2.z*ub.z + v2.w*ub.w;
            a3 += v3.x*ub.x + v3.y*ub.y + v3.z*ub.z + v3.w*ub.w;
            a0 = warp_sum(a0); a1 = warp_sum(a1);
            a2 = warp_sum(a2); a3 = warp_sum(a3);
            if (lane == 0) {
                s_l[m0+0] = a0; s_l[m0+1] = a1;
                s_l[m0+2] = a2; s_l[m0+3] = a3;
            }
        }
        __syncthreads();

        if (hop == 2) {
            if (t < MM) out_pptr[b*MM + t] = s_l[t];
            return;
        }

        if (t < 32) {
            float a = -1e30f, e[4];
            #pragma unroll
            for (int p = 0; p < 4; p++) a = fmaxf(a, s_l[t + 32*p]);
            a = warp_max(a);
            float sm = 0.f;
            #pragma unroll
            for (int p = 0; p < 4; p++) { e[p] = __expf(s_l[t+32*p]-a); sm += e[p]; }
            sm = warp_sum(sm);
            #pragma unroll
            for (int p = 0; p < 4; p++) s_l[t + 32*p] = e[p];
            if (t == 0) s_inv = 1.f / sm;
        }
        __syncthreads();

        const float* MC = g_M + ((size_t)(hop+1)*B + b)*MM*DIM;
        {
            float p = 0.f;
            #pragma unroll 8
            for (int m = q*32; m < q*32 + 32; m++)
                p += s_l[m] * MC[(size_t)m*DIM + col];
            s_p[q*DIM + col] = p;
        }
        __syncthreads();
        if (t < DIM) {
            float o = ((s_p[t] + s_p[DIM+t]) + (s_p[2*DIM+t] + s_p[3*DIM+t])) * s_inv;
            if (hop == 0) g_x512[b*2*DIM + DIM + t] = o;
            s_u[t] += o;
        }
        __syncthreads();
    }
}

// ===== K5: p_vocab — fp16 W, 4-stage cp.async ring, x resident ============
// W stage: [128 v][32 j] halfs, padded row = 36 halfs (72 B, 8B-aligned).
#define TV 128
#define WROWH 36
#define WSTAGEH (TV*WROWH)                         // halfs per stage (4608)
#define K5_SMEM (4*WSTAGEH*2 + 512*16*4)           // 36,864 + 32,768 B
__global__ __launch_bounds__(256) void K5(
    const float* __restrict__ W1b, float* __restrict__ out_pv)
{
    extern __shared__ char sm5raw[];
    __half* W_s = (__half*)sm5raw;                  // 4 stages
    float*  x_s = (float*)(sm5raw + 4*WSTAGEH*2);   // [512][16]

    int t = threadIdx.x;
    int vblk = blockIdx.x * TV;
    int bg = t & 3;                                 // 4 b's
    int vg = t >> 2;                                // 0..63, 2 v each

    // copy granules: 1024 x 8B per stage, 4 per thread
    int cv0 = t >> 3;                               // v base (+32 per i)
    int cseg = t & 7;                               // 8B segment within row

    auto issue_stage = [&](int ch, int s) {
        unsigned int sb = smem_u32(W_s + s*WSTAGEH);
        const __half* gsrc = g_W1h + (size_t)vblk*512 + ch*32;
        #pragma unroll
        for (int i = 0; i < 4; i++) {
            int v = cv0 + 32*i;
            cp_async8(sb + (unsigned int)(v*WROWH + cseg*4)*2,
                      gsrc + (size_t)v*512 + cseg*4);
        }
        cp_commit();
    };

    // x resident (once)
    for (int i = t; i < 512*16; i += 256) {
        int b = i >> 9, j = i & 511;
        x_s[j*16 + b] = g_x512[b*(2*DIM) + j];
    }

    issue_stage(0, 0);
    issue_stage(1, 1);
    issue_stage(2, 2);

    unsigned long long acc2[4];
    #pragma unroll
    for (int i = 0; i < 4; i++) acc2[i] = pack2(0.f, 0.f);

    for (int ch = 0; ch < 16; ch++) {
        if (ch <= 13)      asm volatile("cp.async.wait_group 2;" ::: "memory");
        else if (ch == 14) asm volatile("cp.async.wait_group 1;" ::: "memory");
        else               asm volatile("cp.async.wait_group 0;" ::: "memory");
        __syncthreads();

        if (ch + 3 < 16) issue_stage(ch + 3, (ch + 3) & 3);

        const __half* Wc = W_s + (ch & 3)*WSTAGEH;
        const float*  xc = x_s + ch*32*16;
        int r0 = (vg*2+0)*WROWH, r1 = (vg*2+1)*WROWH;
        #pragma unroll
        for (int jg = 0; jg < 8; jg++) {
            uint2 wau = *(const uint2*)&Wc[r0 + jg*4];   // 4 halfs, v0, j=jg*4..+3
            uint2 wbu = *(const uint2*)&Wc[r1 + jg*4];   // 4 halfs, v1
            float2 wa01 = __half22float2(*(__half2*)&wau.x);
            float2 wa23 = __half22float2(*(__half2*)&wau.y);
            float2 wb01 = __half22float2(*(__half2*)&wbu.x);
            float2 wb23 = __half22float2(*(__half2*)&wbu.y);
            float wa_[4] = {wa01.x, wa01.y, wa23.x, wa23.y};
            float wb_[4] = {wb01.x, wb01.y, wb23.x, wb23.y};
            #pragma unroll
            for (int jj = 0; jj < 4; jj++) {
                int j = jg*4 + jj;
                ulonglong2 xp = *(const ulonglong2*)&xc[j*16 + bg*4];
                unsigned long long w0p = pack2(wa_[jj], wa_[jj]);
                unsigned long long w1p = pack2(wb_[jj], wb_[jj]);
                fma2(acc2[0], w0p, xp.x);  fma2(acc2[1], w0p, xp.y);
                fma2(acc2[2], w1p, xp.x);  fma2(acc2[3], w1p, xp.y);
            }
        }
    }

    #pragma unroll
    for (int q = 0; q < 2; q++) {
        int v = vblk + vg*2 + q;
        float bias = W1b[v];
        float p0, p1, p2, p3;
        unpack2(acc2[q*2+0], p0, p1);
        unpack2(acc2[q*2+1], p2, p3);
        out_pv[(size_t)(bg*4+0)*VOC + v] = p0 + bias;
        out_pv[(size_t)(bg*4+1)*VOC + v] = p1 + bias;
        out_pv[(size_t)(bg*4+2)*VOC + v] = p2 + bias;
        out_pv[(size_t)(bg*4+3)*VOC + v] = p3 + bias;
    }
}

// ================= launch =================
extern "C" void kernel_launch(void* const* d_in, const int* in_sizes, int n_in,
                              void* d_out, int out_size)
{
    const int*   dec       = (const int*)  d_in[0];
    const int*   story     = (const int*)  d_in[1];
    const float* hidden    = (const float*)d_in[2];
    const int*   kb_values = (const int*)  d_in[3];
    const int*   kb_types  = (const int*)  d_in[4];
    const float* C     = (const float*)d_in[7];
    const float* T_emb = (const float*)d_in[8];
    const float* Wq    = (const float*)d_in[9];
    const float* Wk    = (const float*)d_in[10];
    const float* Wv    = (const float*)d_in[11];
    const float* W1w   = (const float*)d_in[12];
    const float* W1b   = (const float*)d_in[13];
    const float* W_ih  = (const float*)d_in[14];
    const float* W_hh  = (const float*)d_in[15];
    const float* b_ih  = (const float*)d_in[16];
    const float* b_hh  = (const float*)d_in[17];

    float* out   = (float*)d_out;
    float* p_ptr = out;
    float* p_voc = out + B*MM;
    float* h_out = out + B*MM + (size_t)B*VOC;

    static int smem_set = 0;
    if (!smem_set) {
        cudaFuncSetAttribute(K5, cudaFuncAttributeMaxDynamicSharedMemorySize, K5_SMEM);
        smem_set = 1;
    }

    K0<<<VOC*DIM/4/256, 256>>>(C);
    K1<<<K1_ROOTS + K1_STORY + K1_GEMV + K1_WCONV, 256>>>(
        kb_values, kb_types, C, T_emb, story, dec, hidden,
        W_ih, W_hh, Wq, b_ih, b_hh, W1w);
    K234<<<B, 1024>>>(Wk, hidden, Wv, h_out, p_ptr);
    K5<<<VOC/TV, 256, K5_SMEM>>>(W1b, p_voc);
}

// round 16
// speedup vs baseline: 1.4486x; 1.4486x over previous
#include <cuda_runtime.h>
#include <cuda_fp16.h>
#include <mma.h>
#include <cstddef>
#include <cstdint>

#define B    16
#define NT   64
#define LN   256
#define LV   4
#define DIM  256
#define VOC  32000
#define MM   128
#define LS   4

// ---------------- scratch (device globals; no allocation) ----------------
__device__ __align__(16) float g_roots[B*NT*DIM];   // 1 MB
__device__ __align__(16) float g_x512[B*2*DIM];     // [u | o0] per b
__device__ __align__(16) float g_M   [4*B*MM*DIM];  // 8 MB: sum_s C[k][story]
__device__ __align__(16) float g_gi  [B*3*DIM];
__device__ __align__(16) float g_gh  [B*3*DIM];
__device__ __align__(16) float g_q   [B*DIM];
__device__ __align__(16) __half g_C0h[VOC*DIM];     // 16.4 MB fp16 C0

__device__ __forceinline__ float warp_sum(float v) {
    #pragma unroll
    for (int o = 16; o; o >>= 1) v += __shfl_xor_sync(0xffffffffu, v, o);
    return v;
}
__device__ __forceinline__ float warp_max(float v) {
    #pragma unroll
    for (int o = 16; o; o >>= 1) v = fmaxf(v, __shfl_xor_sync(0xffffffffu, v, o));
    return v;
}
__device__ __forceinline__ void prefetch_l2(const void* p) {
    asm volatile("prefetch.global.L2 [%0];" :: "l"(p));
}

// ================= K0: convert C0 -> fp16 =================
__global__ __launch_bounds__(256) void K0(const float* __restrict__ C)
{
    size_t i = (size_t)blockIdx.x * 256 + threadIdx.x;
    const float4* C4 = (const float4*)C;
    float4 v = __ldcg(&C4[i]);
    union { __half2 h[2]; uint2 u; } cv;
    cv.h[0] = __floats2half2_rn(v.x, v.y);
    cv.h[1] = __floats2half2_rn(v.z, v.w);
    *(uint2*)&g_C0h[i*4] = cv.u;
}

// ================= K1: fused front-end (R9 structure) =================
#define K1_ROOTS  1024
#define K1_STORY  512
#define K1_GEMV   128
__global__ __launch_bounds__(256) void K1(
    const int* __restrict__ kb_values, const int* __restrict__ kb_types,
    const float* __restrict__ C, const float* __restrict__ T_emb,
    const int* __restrict__ story,
    const int* __restrict__ dec, const float* __restrict__ hidden,
    const float* __restrict__ W_ih, const float* __restrict__ W_hh,
    const float* __restrict__ Wq,
    const float* __restrict__ b_ih, const float* __restrict__ b_hh)
{
    __shared__ union {
        struct { int vals[LN*LV]; int types[LN]; float4 part[3*64]; } rb;
        struct { float x[DIM]; float h[DIM]; } gv;
    } sh;

    int blk = blockIdx.x;
    int t   = threadIdx.x;

    if (blk < K1_ROOTS) {
        int bn = blk;
        int g  = t >> 6;
        int c  = t & 63;
        const int* vp = kb_values + (size_t)bn * LN * LV;
        for (int i = t; i < LN*LV; i += 256) sh.rb.vals[i] = vp[i];
        sh.rb.types[t] = kb_types[(size_t)bn*LN + t];
        __syncthreads();

        const uint2* C0h = (const uint2*)g_C0h;
        const float4* TE = (const float4*)T_emb;
        float4 acc = make_float4(0.f,0.f,0.f,0.f);
        #pragma unroll 4
        for (int l = g; l < LN; l += 4) {
            int4 vv = *(const int4*)&sh.rb.vals[l*4];
            int  ty = sh.rb.types[l];
            float4 te = TE[(size_t)ty*64 + c];
            uint2 r0 = __ldcg(&C0h[(size_t)vv.x*64 + c]);
            uint2 r1 = __ldcg(&C0h[(size_t)vv.y*64 + c]);
            uint2 r2 = __ldcg(&C0h[(size_t)vv.z*64 + c]);
            uint2 r3 = __ldcg(&C0h[(size_t)vv.w*64 + c]);
            __half2 s01 = __hadd2(__hadd2(*(__half2*)&r0.x, *(__half2*)&r1.x),
                                  __hadd2(*(__half2*)&r2.x, *(__half2*)&r3.x));
            __half2 s23 = __hadd2(__hadd2(*(__half2*)&r0.y, *(__half2*)&r1.y),
                                  __hadd2(*(__half2*)&r2.y, *(__half2*)&r3.y));
            float2 f01 = __half22float2(s01);
            float2 f23 = __half22float2(s23);
            acc.x += te.x * f01.x;
            acc.y += te.y * f01.y;
            acc.z += te.z * f23.x;
            acc.w += te.w * f23.y;
        }
        if (g) sh.rb.part[(g-1)*64 + c] = acc;
        __syncthreads();
        if (!g) {
            float4 p0 = sh.rb.part[c], p1 = sh.rb.part[64+c], p2 = sh.rb.part[128+c];
            acc.x += p0.x+p1.x+p2.x;  acc.y += p0.y+p1.y+p2.y;
            acc.z += p0.z+p1.z+p2.z;  acc.w += p0.w+p1.w+p2.w;
            *(float4*)&g_roots[((size_t)bn*64 + c)*4] = acc;
        }
    } else if (blk < K1_ROOTS + K1_STORY) {
        int bm = (blk - K1_ROOTS)*4 + (t >> 6);
        int c  = t & 63;
        const int* st = story + (size_t)bm*LS;
        int i0 = st[0], i1 = st[1], i2 = st[2], i3 = st[3];
        const float4* Cf = (const float4*)C;
        float4* Mf = (float4*)g_M;
        #pragma unroll
        for (int k = 0; k < 4; k++) {
            const float4* Ck = Cf + (size_t)k * VOC * 64;
            float4 a  = __ldcg(&Ck[(size_t)i0*64 + c]);
            float4 b4 = __ldcg(&Ck[(size_t)i1*64 + c]);
            float4 c4 = __ldcg(&Ck[(size_t)i2*64 + c]);
            float4 d4 = __ldcg(&Ck[(size_t)i3*64 + c]);
            float4 r;
            r.x=(a.x+b4.x)+(c4.x+d4.x); r.y=(a.y+b4.y)+(c4.y+d4.y);
            r.z=(a.z+b4.z)+(c4.z+d4.z); r.w=(a.w+b4.w)+(c4.w+d4.w);
            Mf[((size_t)k*B*MM + bm)*64 + c] = r;
        }
    } else {
        int g2 = blk - (K1_ROOTS + K1_STORY);
        int b    = g2 >> 3;
        int part = g2 & 7;
        int w = t >> 5, lane = t & 31;

        if (t < DIM) {
            sh.gv.h[t] = hidden[b*DIM + t];
            sh.gv.x[t] = C[(size_t)dec[b]*DIM + t];
        }
        __syncthreads();
        const float4* x4 = (const float4*)sh.gv.x;
        const float4* h4 = (const float4*)sh.gv.h;

        int base = part*224;
        #pragma unroll 4
        for (int i = 0; i < 28; i++) {
            int o = base + w + 8*i;
            const float* Wrow;
            const float4* v;
            if (o < 768)        { Wrow = W_ih + (size_t)o*DIM;        v = x4; }
            else if (o < 1536)  { Wrow = W_hh + (size_t)(o-768)*DIM;  v = h4; }
            else                { Wrow = Wq   + (size_t)(o-1536)*DIM; v = h4; }
            const float4* W4 = (const float4*)Wrow;
            float4 wa = W4[lane],      va = v[lane];
            float4 wb = W4[lane + 32], vb = v[lane + 32];
            float s = wa.x*va.x + wa.y*va.y + wa.z*va.z + wa.w*va.w
                    + wb.x*vb.x + wb.y*vb.y + wb.z*vb.z + wb.w*vb.w;
            s = warp_sum(s);
            if (lane == 0) {
                if (o < 768)       g_gi[b*768 + o]        = s + b_ih[o];
                else if (o < 1536) g_gh[b*768 + (o-768)]  = s + b_hh[o-768];
                else               g_q [b*DIM + (o-1536)] = s;
            }
        }
    }
}

// ===== K234: kv+GRU+attention+3 hops, one block per b (1024 threads) ======
__global__ __launch_bounds__(1024) void K234(
    const float* __restrict__ Wk, const float* __restrict__ hidden,
    const float* __restrict__ Wv, float* __restrict__ out_hnew,
    float* __restrict__ out_pptr)
{
    int b = blockIdx.x, t = threadIdx.x;
    int w = t >> 5, lane = t & 31;
    int col = t & 255, q = t >> 8;
    __shared__ float s_q[DIM], s_kv[DIM], s_hn[DIM], s_sc[NT],
                     s_p[4*DIM], s_rbar[DIM], s_feat[DIM],
                     s_u[DIM], s_l[MM];
    __shared__ float s_inv;

    {
        const char* mb = (const char*)g_M;
        #pragma unroll
        for (int k = 0; k < 4; k++)
            prefetch_l2(mb + ((size_t)(k*B + b)*MM*DIM)*4 + (size_t)t*128);
    }

    if (t < DIM) s_q[t] = g_q[b*DIM + t];
    __syncthreads();

    {
        float p = 0.f;
        #pragma unroll 8
        for (int k = q*64; k < q*64 + 64; k++)
            p += Wk[(size_t)k*DIM + col] * s_q[k];
        s_p[q*DIM + col] = p;
    }
    __syncthreads();
    if (t < DIM) {
        s_kv[t] = (s_p[t] + s_p[DIM+t]) + (s_p[2*DIM+t] + s_p[3*DIM+t]);
        float gi0 = g_gi[b*768 + t],         gh0 = g_gh[b*768 + t];
        float gi1 = g_gi[b*768 + DIM + t],   gh1 = g_gh[b*768 + DIM + t];
        float gi2 = g_gi[b*768 + 2*DIM + t], gh2 = g_gh[b*768 + 2*DIM + t];
        float h   = hidden[b*DIM + t];
        float r  = 1.f / (1.f + __expf(-(gi0 + gh0)));
        float z  = 1.f / (1.f + __expf(-(gi1 + gh1)));
        float n  = tanhf(gi2 + r * gh2);
        float hn = (1.f - z) * n + z * h;
        s_hn[t] = hn;
        out_hnew[b*DIM + t] = hn;
    }
    __syncthreads();

    const float4* kv4 = (const float4*)s_kv;
    #pragma unroll
    for (int i = 0; i < 2; i++) {
        int n = w + 32*i;
        const float4* r4 = (const float4*)(g_roots + ((size_t)b*NT + n)*DIM);
        float4 ra = r4[lane], ka = kv4[lane];
        float4 rb = r4[lane+32], kb = kv4[lane+32];
        float sc = ra.x*ka.x + ra.y*ka.y + ra.z*ka.z + ra.w*ka.w
                 + rb.x*kb.x + rb.y*kb.y + rb.z*kb.z + rb.w*kb.w;
        float rs = (ra.x+ra.y+ra.z+ra.w) + (rb.x+rb.y+rb.z+rb.w);
        sc = warp_sum(sc);
        rs = warp_sum(rs);
        if (lane == 0) s_sc[n] = (rs == 0.0f) ? sc - 1e9f : sc;
    }
    __syncthreads();

    if (t < 32) {
        float a = fmaxf(s_sc[t], s_sc[t+32]);
        a = warp_max(a);
        float e0 = __expf(s_sc[t]-a), e1 = __expf(s_sc[t+32]-a);
        float inv = 1.f / warp_sum(e0 + e1);
        s_sc[t] = e0*inv; s_sc[t+32] = e1*inv;
    }
    __syncthreads();

    {
        float p = 0.f;
        #pragma unroll 8
        for (int n = q*16; n < q*16 + 16; n++)
            p += s_sc[n] * g_roots[((size_t)b*NT + n)*DIM + col];
        s_p[q*DIM + col] = p;
    }
    __syncthreads();
    if (t < DIM)
        s_rbar[t] = (s_p[t] + s_p[DIM+t]) + (s_p[2*DIM+t] + s_p[3*DIM+t]);
    __syncthreads();

    const float4* rb4 = (const float4*)s_rbar;
    #pragma unroll
    for (int i = 0; i < 8; i++) {
        int k = w + 32*i;
        const float4* W4 = (const float4*)(Wv + (size_t)k*DIM);
        float4 wa = W4[lane],    va = rb4[lane];
        float4 wb = W4[lane+32], vb = rb4[lane+32];
        float s = wa.x*va.x + wa.y*va.y + wa.z*va.z + wa.w*va.w
                + wb.x*vb.x + wb.y*vb.y + wb.z*vb.z + wb.w*vb.w;
        s = warp_sum(s);
        if (lane == 0) s_feat[k] = s;
    }
    __syncthreads();

    if (t < DIM) {
        float u = s_hn[t] + s_feat[t];
        s_u[t] = u;
        g_x512[b*2*DIM + t] = u;
    }
    __syncthreads();

    for (int hop = 0; hop < 3; hop++) {
        const float* MA = g_M + ((size_t)hop*B + b)*MM*DIM;
        const float4* u4 = (const float4*)s_u;
        {
            int m0 = w*4;
            float4 ua = u4[lane], ub = u4[lane+32];
            const float4* r0 = (const float4*)(MA + (size_t)(m0+0)*DIM);
            const float4* r1 = (const float4*)(MA + (size_t)(m0+1)*DIM);
            const float4* r2 = (const float4*)(MA + (size_t)(m0+2)*DIM);
            const float4* r3 = (const float4*)(MA + (size_t)(m0+3)*DIM);
            float4 v0 = r0[lane], v1 = r1[lane], v2 = r2[lane], v3 = r3[lane];
            float a0 = v0.x*ua.x + v0.y*ua.y + v0.z*ua.z + v0.w*ua.w;
            float a1 = v1.x*ua.x + v1.y*ua.y + v1.z*ua.z + v1.w*ua.w;
            float a2 = v2.x*ua.x + v2.y*ua.y + v2.z*ua.z + v2.w*ua.w;
            float a3 = v3.x*ua.x + v3.y*ua.y + v3.z*ua.z + v3.w*ua.w;
            v0 = r0[lane+32]; v1 = r1[lane+32]; v2 = r2[lane+32]; v3 = r3[lane+32];
            a0 += v0.x*ub.x + v0.y*ub.y + v0.z*ub.z + v0.w*ub.w;
            a1 += v1.x*ub.x + v1.y*ub.y + v1.z*ub.z + v1.w*ub.w;
            a2 += v2.x*ub.x + v2.y*ub.y + v2.z*ub.z + v2.w*ub.w;
            a3 += v3.x*ub.x + v3.y*ub.y + v3.z*ub.z + v3.w*ub.w;
            a0 = warp_sum(a0); a1 = warp_sum(a1);
            a2 = warp_sum(a2); a3 = warp_sum(a3);
            if (lane == 0) {
                s_l[m0+0] = a0; s_l[m0+1] = a1;
                s_l[m0+2] = a2; s_l[m0+3] = a3;
            }
        }
        __syncthreads();

        if (hop == 2) {
            if (t < MM) out_pptr[b*MM + t] = s_l[t];
            return;
        }

        if (t < 32) {
            float a = -1e30f, e[4];
            #pragma unroll
            for (int p = 0; p < 4; p++) a = fmaxf(a, s_l[t + 32*p]);
            a = warp_max(a);
            float sm = 0.f;
            #pragma unroll
            for (int p = 0; p < 4; p++) { e[p] = __expf(s_l[t+32*p]-a); sm += e[p]; }
            sm = warp_sum(sm);
            #pragma unroll
            for (int p = 0; p < 4; p++) s_l[t + 32*p] = e[p];
            if (t == 0) s_inv = 1.f / sm;
        }
        __syncthreads();

        const float* MC = g_M + ((size_t)(hop+1)*B + b)*MM*DIM;
        {
            float p = 0.f;
            #pragma unroll 8
            for (int m = q*32; m < q*32 + 32; m++)
                p += s_l[m] * MC[(size_t)m*DIM + col];
            s_p[q*DIM + col] = p;
        }
        __syncthreads();
        if (t < DIM) {
            float o = ((s_p[t] + s_p[DIM+t]) + (s_p[2*DIM+t] + s_p[3*DIM+t])) * s_inv;
            if (hop == 0) g_x512[b*2*DIM + DIM + t] = o;
            s_u[t] += o;
        }
        __syncthreads();
    }
}

// ===== K5: p_vocab via wmma (HMMA) — D[16b x 128v] = x_h @ W_h^T ==========
// 8 warps, each owns one 16-v accumulator tile. W staged per-64k chunk
// fp32->fp16 with register prefetch (LDGs of chunk n+1 overlap compute of n).
#define TV 128
#define XLD 520                         // x row stride (halfs): mult of 8, 16B rows
#define WLD 72                          // W row stride (halfs)
#define ALD 136                         // acc row stride (floats)
#define SM_X 0                          // 16*520*2      = 16640 B
#define SM_W 16640                      // 128*72*2      = 18432 B
#define SM_ACC (16640 + 18432)          // 16*136*4      =  8704 B
#define K5_SMEM (SM_ACC + 16*ALD*4)

__global__ __launch_bounds__(256) void K5(
    const float* __restrict__ W1w, const float* __restrict__ W1b,
    float* __restrict__ out_pv)
{
    using namespace nvcuda;
    extern __shared__ char sm5[];
    __half* x_h = (__half*)(sm5 + SM_X);
    __half* W_h = (__half*)(sm5 + SM_W);
    float*  a_f = (float*) (sm5 + SM_ACC);

    int t = threadIdx.x;
    int wid = t >> 5;
    int vblk = blockIdx.x * TV;

    // per-thread W granule mapping (fixed across chunks)
    int wrow = t >> 4;                  // v row 0..15 (+16 per i)
    int wc4  = t & 15;                  // float4 col within 64-k chunk

    const float4* Wsrc = (const float4*)(W1w + (size_t)vblk*512);
    float4 pre[8];

    // prime chunk 0 LDGs
    #pragma unroll
    for (int i = 0; i < 8; i++)
        pre[i] = __ldcg(&Wsrc[(size_t)(wrow + 16*i)*128 + wc4]);

    // stage x (16 x 512 fp16), coalesced
    for (int i = t; i < 4096; i += 256) {
        int b = i >> 8, jp = i & 255;
        float2 xv = *(const float2*)&g_x512[b*512 + jp*2];
        *(__half2*)&x_h[b*XLD + jp*2] = __floats2half2_rn(xv.x, xv.y);
    }

    wmma::fragment<wmma::accumulator, 16, 16, 16, float> acc;
    wmma::fill_fragment(acc, 0.0f);

    for (int ch = 0; ch < 8; ch++) {
        // store current chunk's registers to smem (fp16)
        #pragma unroll
        for (int i = 0; i < 8; i++) {
            int row = wrow + 16*i;
            __half2 h0 = __floats2half2_rn(pre[i].x, pre[i].y);
            __half2 h1 = __floats2half2_rn(pre[i].z, pre[i].w);
            *(__half2*)&W_h[row*WLD + wc4*4]     = h0;
            *(__half2*)&W_h[row*WLD + wc4*4 + 2] = h1;
        }
        __syncthreads();

        // issue next chunk's LDGs (overlap with MMA below)
        if (ch < 7) {
            const float4* src = Wsrc + (ch + 1)*16;
            #pragma unroll
            for (int i = 0; i < 8; i++)
                pre[i] = __ldcg(&src[(size_t)(wrow + 16*i)*128 + wc4]);
        }

        // 4 k-steps of 16 on this chunk
        #pragma unroll
        for (int ks = 0; ks < 4; ks++) {
            wmma::fragment<wmma::matrix_a, 16, 16, 16, __half, wmma::row_major> af;
            wmma::fragment<wmma::matrix_b, 16, 16, 16, __half, wmma::col_major> bf;
            wmma::load_matrix_sync(af, x_h + ch*64 + ks*16, XLD);
            wmma::load_matrix_sync(bf, W_h + wid*16*WLD + ks*16, WLD);
            wmma::mma_sync(acc, af, bf, acc);
        }
        __syncthreads();     // compute done before next STS overwrites W_h
    }

    // epilogue: acc -> smem -> +bias -> coalesced STG
    wmma::store_matrix_sync(a_f + wid*16, acc, ALD, wmma::mem_row_major);
    __syncthreads();
    #pragma unroll
    for (int i = 0; i < 8; i++) {
        int idx = i*256 + t;            // 0..2047
        int b   = idx >> 7;
        int c   = idx & 127;
        out_pv[(size_t)b*VOC + vblk + c] = a_f[b*ALD + c] + W1b[vblk + c];
    }
}

// ================= launch =================
extern "C" void kernel_launch(void* const* d_in, const int* in_sizes, int n_in,
                              void* d_out, int out_size)
{
    const int*   dec       = (const int*)  d_in[0];
    const int*   story     = (const int*)  d_in[1];
    const float* hidden    = (const float*)d_in[2];
    const int*   kb_values = (const int*)  d_in[3];
    const int*   kb_types  = (const int*)  d_in[4];
    const float* C     = (const float*)d_in[7];
    const float* T_emb = (const float*)d_in[8];
    const float* Wq    = (const float*)d_in[9];
    const float* Wk    = (const float*)d_in[10];
    const float* Wv    = (const float*)d_in[11];
    const float* W1w   = (const float*)d_in[12];
    const float* W1b   = (const float*)d_in[13];
    const float* W_ih  = (const float*)d_in[14];
    const float* W_hh  = (const float*)d_in[15];
    const float* b_ih  = (const float*)d_in[16];
    const float* b_hh  = (const float*)d_in[17];

    float* out   = (float*)d_out;
    float* p_ptr = out;
    float* p_voc = out + B*MM;
    float* h_out = out + B*MM + (size_t)B*VOC;

    static int smem_set = 0;
    if (!smem_set) {
        cudaFuncSetAttribute(K5, cudaFuncAttributeMaxDynamicSharedMemorySize, K5_SMEM);
        smem_set = 1;
    }

    K0<<<VOC*DIM/4/256, 256>>>(C);
    K1<<<K1_ROOTS + K1_STORY + K1_GEMV, 256>>>(
        kb_values, kb_types, C, T_emb, story, dec, hidden,
        W_ih, W_hh, Wq, b_ih, b_hh);
    K234<<<B, 1024>>>(Wk, hidden, Wv, h_out, p_ptr);
    K5<<<VOC/TV, 256, K5_SMEM>>>(W1w, W1b, p_voc);
}

// round 17
// speedup vs baseline: 1.4935x; 1.0310x over previous
#include <cuda_runtime.h>
#include <cuda_fp16.h>
#include <mma.h>
#include <cstddef>
#include <cstdint>

#define B    16
#define NT   64
#define LN   256
#define LV   4
#define DIM  256
#define VOC  32000
#define MM   128
#define LS   4

// ---------------- scratch (device globals; no allocation) ----------------
__device__ __align__(16) float g_roots[B*NT*DIM];   // 1 MB
__device__ __align__(16) float g_x512[B*2*DIM];     // [u | o0] per b
__device__ __align__(16) float g_M   [4*B*MM*DIM];  // 8 MB: sum_s C[k][story]
__device__ __align__(16) float g_gi  [B*3*DIM];
__device__ __align__(16) float g_gh  [B*3*DIM];
__device__ __align__(16) float g_q   [B*DIM];
__device__ __align__(16) __half g_C0h[VOC*DIM];     // 16.4 MB fp16 C0
__device__ __align__(16) __half g_W1h[VOC*2*DIM];   // 32.8 MB fp16 W1w [v][j]

__device__ __forceinline__ float warp_sum(float v) {
    #pragma unroll
    for (int o = 16; o; o >>= 1) v += __shfl_xor_sync(0xffffffffu, v, o);
    return v;
}
__device__ __forceinline__ float warp_max(float v) {
    #pragma unroll
    for (int o = 16; o; o >>= 1) v = fmaxf(v, __shfl_xor_sync(0xffffffffu, v, o));
    return v;
}
__device__ __forceinline__ void prefetch_l2(const void* p) {
    asm volatile("prefetch.global.L2 [%0];" :: "l"(p));
}
__device__ __forceinline__ unsigned int smem_u32(const void* p) {
    unsigned int a;
    asm("{ .reg .u64 t; cvta.to.shared.u64 t, %1; cvt.u32.u64 %0, t; }"
        : "=r"(a) : "l"(p));
    return a;
}
__device__ __forceinline__ void cp_async16(unsigned int dst, const void* src) {
    asm volatile("cp.async.cg.shared.global [%0], [%1], 16;" :: "r"(dst), "l"(src));
}
__device__ __forceinline__ void cp_commit() {
    asm volatile("cp.async.commit_group;" ::: "memory");
}

// ================= K0: convert C0 -> fp16 =================
__global__ __launch_bounds__(256) void K0(const float* __restrict__ C)
{
    size_t i = (size_t)blockIdx.x * 256 + threadIdx.x;
    const float4* C4 = (const float4*)C;
    float4 v = __ldcg(&C4[i]);
    union { __half2 h[2]; uint2 u; } cv;
    cv.h[0] = __floats2half2_rn(v.x, v.y);
    cv.h[1] = __floats2half2_rn(v.z, v.w);
    *(uint2*)&g_C0h[i*4] = cv.u;
}

// ================= K1: fused front-end (R9 structure) =================
#define K1_ROOTS  1024
#define K1_STORY  512
#define K1_GEMV   128
__global__ __launch_bounds__(256) void K1(
    const int* __restrict__ kb_values, const int* __restrict__ kb_types,
    const float* __restrict__ C, const float* __restrict__ T_emb,
    const int* __restrict__ story,
    const int* __restrict__ dec, const float* __restrict__ hidden,
    const float* __restrict__ W_ih, const float* __restrict__ W_hh,
    const float* __restrict__ Wq,
    const float* __restrict__ b_ih, const float* __restrict__ b_hh)
{
    __shared__ union {
        struct { int vals[LN*LV]; int types[LN]; float4 part[3*64]; } rb;
        struct { float x[DIM]; float h[DIM]; } gv;
    } sh;

    int blk = blockIdx.x;
    int t   = threadIdx.x;

    if (blk < K1_ROOTS) {
        int bn = blk;
        int g  = t >> 6;
        int c  = t & 63;
        const int* vp = kb_values + (size_t)bn * LN * LV;
        for (int i = t; i < LN*LV; i += 256) sh.rb.vals[i] = vp[i];
        sh.rb.types[t] = kb_types[(size_t)bn*LN + t];
        __syncthreads();

        const uint2* C0h = (const uint2*)g_C0h;
        const float4* TE = (const float4*)T_emb;
        float4 acc = make_float4(0.f,0.f,0.f,0.f);
        #pragma unroll 4
        for (int l = g; l < LN; l += 4) {
            int4 vv = *(const int4*)&sh.rb.vals[l*4];
            int  ty = sh.rb.types[l];
            float4 te = TE[(size_t)ty*64 + c];
            uint2 r0 = __ldcg(&C0h[(size_t)vv.x*64 + c]);
            uint2 r1 = __ldcg(&C0h[(size_t)vv.y*64 + c]);
            uint2 r2 = __ldcg(&C0h[(size_t)vv.z*64 + c]);
            uint2 r3 = __ldcg(&C0h[(size_t)vv.w*64 + c]);
            __half2 s01 = __hadd2(__hadd2(*(__half2*)&r0.x, *(__half2*)&r1.x),
                                  __hadd2(*(__half2*)&r2.x, *(__half2*)&r3.x));
            __half2 s23 = __hadd2(__hadd2(*(__half2*)&r0.y, *(__half2*)&r1.y),
                                  __hadd2(*(__half2*)&r2.y, *(__half2*)&r3.y));
            float2 f01 = __half22float2(s01);
            float2 f23 = __half22float2(s23);
            acc.x += te.x * f01.x;
            acc.y += te.y * f01.y;
            acc.z += te.z * f23.x;
            acc.w += te.w * f23.y;
        }
        if (g) sh.rb.part[(g-1)*64 + c] = acc;
        __syncthreads();
        if (!g) {
            float4 p0 = sh.rb.part[c], p1 = sh.rb.part[64+c], p2 = sh.rb.part[128+c];
            acc.x += p0.x+p1.x+p2.x;  acc.y += p0.y+p1.y+p2.y;
            acc.z += p0.z+p1.z+p2.z;  acc.w += p0.w+p1.w+p2.w;
            *(float4*)&g_roots[((size_t)bn*64 + c)*4] = acc;
        }
    } else if (blk < K1_ROOTS + K1_STORY) {
        int bm = (blk - K1_ROOTS)*4 + (t >> 6);
        int c  = t & 63;
        const int* st = story + (size_t)bm*LS;
        int i0 = st[0], i1 = st[1], i2 = st[2], i3 = st[3];
        const float4* Cf = (const float4*)C;
        float4* Mf = (float4*)g_M;
        #pragma unroll
        for (int k = 0; k < 4; k++) {
            const float4* Ck = Cf + (size_t)k * VOC * 64;
            float4 a  = __ldcg(&Ck[(size_t)i0*64 + c]);
            float4 b4 = __ldcg(&Ck[(size_t)i1*64 + c]);
            float4 c4 = __ldcg(&Ck[(size_t)i2*64 + c]);
            float4 d4 = __ldcg(&Ck[(size_t)i3*64 + c]);
            float4 r;
            r.x=(a.x+b4.x)+(c4.x+d4.x); r.y=(a.y+b4.y)+(c4.y+d4.y);
            r.z=(a.z+b4.z)+(c4.z+d4.z); r.w=(a.w+b4.w)+(c4.w+d4.w);
            Mf[((size_t)k*B*MM + bm)*64 + c] = r;
        }
    } else {
        int g2 = blk - (K1_ROOTS + K1_STORY);
        int b    = g2 >> 3;
        int part = g2 & 7;
        int w = t >> 5, lane = t & 31;

        if (t < DIM) {
            sh.gv.h[t] = hidden[b*DIM + t];
            sh.gv.x[t] = C[(size_t)dec[b]*DIM + t];
        }
        __syncthreads();
        const float4* x4 = (const float4*)sh.gv.x;
        const float4* h4 = (const float4*)sh.gv.h;

        int base = part*224;
        #pragma unroll 4
        for (int i = 0; i < 28; i++) {
            int o = base + w + 8*i;
            const float* Wrow;
            const float4* v;
            if (o < 768)        { Wrow = W_ih + (size_t)o*DIM;        v = x4; }
            else if (o < 1536)  { Wrow = W_hh + (size_t)(o-768)*DIM;  v = h4; }
            else                { Wrow = Wq   + (size_t)(o-1536)*DIM; v = h4; }
            const float4* W4 = (const float4*)Wrow;
            float4 wa = W4[lane],      va = v[lane];
            float4 wb = W4[lane + 32], vb = v[lane + 32];
            float s = wa.x*va.x + wa.y*va.y + wa.z*va.z + wa.w*va.w
                    + wb.x*vb.x + wb.y*vb.y + wb.z*vb.z + wb.w*vb.w;
            s = warp_sum(s);
            if (lane == 0) {
                if (o < 768)       g_gi[b*768 + o]        = s + b_ih[o];
                else if (o < 1536) g_gh[b*768 + (o-768)]  = s + b_hh[o-768];
                else               g_q [b*DIM + (o-1536)] = s;
            }
        }
    }
}

// ===== K234: blocks [0,16): kv+GRU+attention+3 hops per b =================
// blocks [16,144): stream-convert W1w -> fp16 g_W1h with .cs hints (runs on
// the ~130 idle SMs; evict-first keeps g_M L2-resident for the hop loop).
#define K234_CONV 128
__global__ __launch_bounds__(1024) void K234(
    const float* __restrict__ Wk, const float* __restrict__ hidden,
    const float* __restrict__ Wv, const float* __restrict__ W1w,
    float* __restrict__ out_hnew, float* __restrict__ out_pptr)
{
    int t = threadIdx.x;

    if (blockIdx.x >= B) {
        // ---- W1w fp32 -> fp16 streaming convert ----
        int pb = blockIdx.x - B;                        // 0..127
        const float4* W4 = (const float4*)W1w;
        const size_t total = (size_t)VOC*512/4;          // 4,096,000
        #pragma unroll 4
        for (int i = 0; i < 32; i++) {
            size_t idx = (size_t)pb*1024 + t + (size_t)i*(K234_CONV*1024);
            if (idx < total) {
                float4 v = __ldcs(&W4[idx]);
                union { __half2 h[2]; uint2 u; } cv;
                cv.h[0] = __floats2half2_rn(v.x, v.y);
                cv.h[1] = __floats2half2_rn(v.z, v.w);
                asm volatile("st.global.cs.v2.u32 [%0], {%1, %2};"
                             :: "l"(&g_W1h[idx*4]), "r"(cv.u.x), "r"(cv.u.y) : "memory");
            }
        }
        return;
    }

    int b = blockIdx.x;
    int w = t >> 5, lane = t & 31;
    int col = t & 255, q = t >> 8;
    __shared__ float s_q[DIM], s_kv[DIM], s_hn[DIM], s_sc[NT],
                     s_p[4*DIM], s_rbar[DIM], s_feat[DIM],
                     s_u[DIM], s_l[MM];
    __shared__ float s_inv;

    {
        const char* mb = (const char*)g_M;
        #pragma unroll
        for (int k = 0; k < 4; k++)
            prefetch_l2(mb + ((size_t)(k*B + b)*MM*DIM)*4 + (size_t)t*128);
    }

    if (t < DIM) s_q[t] = g_q[b*DIM + t];
    __syncthreads();

    {
        float p = 0.f;
        #pragma unroll 8
        for (int k = q*64; k < q*64 + 64; k++)
            p += Wk[(size_t)k*DIM + col] * s_q[k];
        s_p[q*DIM + col] = p;
    }
    __syncthreads();
    if (t < DIM) {
        s_kv[t] = (s_p[t] + s_p[DIM+t]) + (s_p[2*DIM+t] + s_p[3*DIM+t]);
        float gi0 = g_gi[b*768 + t],         gh0 = g_gh[b*768 + t];
        float gi1 = g_gi[b*768 + DIM + t],   gh1 = g_gh[b*768 + DIM + t];
        float gi2 = g_gi[b*768 + 2*DIM + t], gh2 = g_gh[b*768 + 2*DIM + t];
        float h   = hidden[b*DIM + t];
        float r  = 1.f / (1.f + __expf(-(gi0 + gh0)));
        float z  = 1.f / (1.f + __expf(-(gi1 + gh1)));
        float n  = tanhf(gi2 + r * gh2);
        float hn = (1.f - z) * n + z * h;
        s_hn[t] = hn;
        out_hnew[b*DIM + t] = hn;
    }
    __syncthreads();

    const float4* kv4 = (const float4*)s_kv;
    #pragma unroll
    for (int i = 0; i < 2; i++) {
        int n = w + 32*i;
        const float4* r4 = (const float4*)(g_roots + ((size_t)b*NT + n)*DIM);
        float4 ra = r4[lane], ka = kv4[lane];
        float4 rb = r4[lane+32], kb = kv4[lane+32];
        float sc = ra.x*ka.x + ra.y*ka.y + ra.z*ka.z + ra.w*ka.w
                 + rb.x*kb.x + rb.y*kb.y + rb.z*kb.z + rb.w*kb.w;
        float rs = (ra.x+ra.y+ra.z+ra.w) + (rb.x+rb.y+rb.z+rb.w);
        sc = warp_sum(sc);
        rs = warp_sum(rs);
        if (lane == 0) s_sc[n] = (rs == 0.0f) ? sc - 1e9f : sc;
    }
    __syncthreads();

    if (t < 32) {
        float a = fmaxf(s_sc[t], s_sc[t+32]);
        a = warp_max(a);
        float e0 = __expf(s_sc[t]-a), e1 = __expf(s_sc[t+32]-a);
        float inv = 1.f / warp_sum(e0 + e1);
        s_sc[t] = e0*inv; s_sc[t+32] = e1*inv;
    }
    __syncthreads();

    {
        float p = 0.f;
        #pragma unroll 8
        for (int n = q*16; n < q*16 + 16; n++)
            p += s_sc[n] * g_roots[((size_t)b*NT + n)*DIM + col];
        s_p[q*DIM + col] = p;
    }
    __syncthreads();
    if (t < DIM)
        s_rbar[t] = (s_p[t] + s_p[DIM+t]) + (s_p[2*DIM+t] + s_p[3*DIM+t]);
    __syncthreads();

    const float4* rb4 = (const float4*)s_rbar;
    #pragma unroll
    for (int i = 0; i < 8; i++) {
        int k = w + 32*i;
        const float4* W4 = (const float4*)(Wv + (size_t)k*DIM);
        float4 wa = W4[lane],    va = rb4[lane];
        float4 wb = W4[lane+32], vb = rb4[lane+32];
        float s = wa.x*va.x + wa.y*va.y + wa.z*va.z + wa.w*va.w
                + wb.x*vb.x + wb.y*vb.y + wb.z*vb.z + wb.w*vb.w;
        s = warp_sum(s);
        if (lane == 0) s_feat[k] = s;
    }
    __syncthreads();

    if (t < DIM) {
        float u = s_hn[t] + s_feat[t];
        s_u[t] = u;
        g_x512[b*2*DIM + t] = u;
    }
    __syncthreads();

    for (int hop = 0; hop < 3; hop++) {
        const float* MA = g_M + ((size_t)hop*B + b)*MM*DIM;
        const float4* u4 = (const float4*)s_u;
        {
            int m0 = w*4;
            float4 ua = u4[lane], ub = u4[lane+32];
            const float4* r0 = (const float4*)(MA + (size_t)(m0+0)*DIM);
            const float4* r1 = (const float4*)(MA + (size_t)(m0+1)*DIM);
            const float4* r2 = (const float4*)(MA + (size_t)(m0+2)*DIM);
            const float4* r3 = (const float4*)(MA + (size_t)(m0+3)*DIM);
            float4 v0 = r0[lane], v1 = r1[lane], v2 = r2[lane], v3 = r3[lane];
            float a0 = v0.x*ua.x + v0.y*ua.y + v0.z*ua.z + v0.w*ua.w;
            float a1 = v1.x*ua.x + v1.y*ua.y + v1.z*ua.z + v1.w*ua.w;
            float a2 = v2.x*ua.x + v2.y*ua.y + v2.z*ua.z + v2.w*ua.w;
            float a3 = v3.x*ua.x + v3.y*ua.y + v3.z*ua.z + v3.w*ua.w;
            v0 = r0[lane+32]; v1 = r1[lane+32]; v2 = r2[lane+32]; v3 = r3[lane+32];
            a0 += v0.x*ub.x + v0.y*ub.y + v0.z*ub.z + v0.w*ub.w;
            a1 += v1.x*ub.x + v1.y*ub.y + v1.z*ub.z + v1.w*ub.w;
            a2 += v2.x*ub.x + v2.y*ub.y + v2.z*ub.z + v2.w*ub.w;
            a3 += v3.x*ub.x + v3.y*ub.y + v3.z*ub.z + v3.w*ub.w;
            a0 = warp_sum(a0); a1 = warp_sum(a1);
            a2 = warp_sum(a2); a3 = warp_sum(a3);
            if (lane == 0) {
                s_l[m0+0] = a0; s_l[m0+1] = a1;
                s_l[m0+2] = a2; s_l[m0+3] = a3;
            }
        }
        __syncthreads();

        if (hop == 2) {
            if (t < MM) out_pptr[b*MM + t] = s_l[t];
            return;
        }

        if (t < 32) {
            float a = -1e30f, e[4];
            #pragma unroll
            for (int p = 0; p < 4; p++) a = fmaxf(a, s_l[t + 32*p]);
            a = warp_max(a);
            float sm = 0.f;
            #pragma unroll
            for (int p = 0; p < 4; p++) { e[p] = __expf(s_l[t+32*p]-a); sm += e[p]; }
            sm = warp_sum(sm);
            #pragma unroll
            for (int p = 0; p < 4; p++) s_l[t + 32*p] = e[p];
            if (t == 0) s_inv = 1.f / sm;
        }
        __syncthreads();

        const float* MC = g_M + ((size_t)(hop+1)*B + b)*MM*DIM;
        {
            float p = 0.f;
            #pragma unroll 8
            for (int m = q*32; m < q*32 + 32; m++)
                p += s_l[m] * MC[(size_t)m*DIM + col];
            s_p[q*DIM + col] = p;
        }
        __syncthreads();
        if (t < DIM) {
            float o = ((s_p[t] + s_p[DIM+t]) + (s_p[2*DIM+t] + s_p[3*DIM+t])) * s_inv;
            if (hop == 0) g_x512[b*2*DIM + DIM + t] = o;
            s_u[t] += o;
        }
        __syncthreads();
    }
}

// ===== K5: p_vocab via wmma — fp16 W via 4-stage cp.async ring ============
#define TV 128
#define XLD 520                          // x row stride (halfs)
#define WLD 72                           // W row stride (halfs); 144 B, 16B-mult
#define ALD 136                          // acc row stride (floats)
#define NSTG 4
#define WSTGH (TV*WLD)                   // halfs per stage (9216)
#define SM_X 0                           // 16*520*2  = 16640 B
#define SM_W 16640                       // 4*9216*2  = 73728 B
#define SM_ACC (16640 + NSTG*WSTGH*2)
#define K5_SMEM (SM_ACC + 16*ALD*4)

__global__ __launch_bounds__(256) void K5(
    const float* __restrict__ W1b, float* __restrict__ out_pv)
{
    using namespace nvcuda;
    extern __shared__ char sm5[];
    __half* x_h = (__half*)(sm5 + SM_X);
    __half* W_s = (__half*)(sm5 + SM_W);
    float*  a_f = (float*) (sm5 + SM_ACC);

    int t = threadIdx.x;
    int wid = t >> 5;
    int vblk = blockIdx.x * TV;

    // stage x (16 x 512 fp16)
    for (int i = t; i < 4096; i += 256) {
        int b = i >> 8, jp = i & 255;
        float2 xv = *(const float2*)&g_x512[b*512 + jp*2];
        *(__half2*)&x_h[b*XLD + jp*2] = __floats2half2_rn(xv.x, xv.y);
    }

    // stage issuer: 128 rows x 64 halfs = 1024 x 16B granules, 4/thread
    auto issue = [&](int ch, int s) {
        unsigned int sb = smem_u32(W_s + s*WSTGH);
        const __half* src = g_W1h + (size_t)vblk*512 + ch*64;
        #pragma unroll
        for (int i = 0; i < 4; i++) {
            int g = t + 256*i;
            int row = g >> 3, seg = g & 7;
            cp_async16(sb + (unsigned int)(row*WLD + seg*8)*2,
                       src + (size_t)row*512 + seg*8);
        }
        cp_commit();
    };

    issue(0, 0);
    issue(1, 1);
    issue(2, 2);

    wmma::fragment<wmma::accumulator, 16, 16, 16, float> acc;
    wmma::fill_fragment(acc, 0.0f);

    for (int ch = 0; ch < 8; ch++) {
        if (ch <= 5)      asm volatile("cp.async.wait_group 2;" ::: "memory");
        else if (ch == 6) asm volatile("cp.async.wait_group 1;" ::: "memory");
        else              asm volatile("cp.async.wait_group 0;" ::: "memory");
        __syncthreads();     // copies visible; prior compute done before refill

        if (ch + 3 < 8) issue(ch + 3, (ch + 3) & 3);

        const __half* Wc = W_s + (ch & 3)*WSTGH;
        #pragma unroll
        for (int ks = 0; ks < 4; ks++) {
            wmma::fragment<wmma::matrix_a, 16, 16, 16, __half, wmma::row_major> af;
            wmma::fragment<wmma::matrix_b, 16, 16, 16, __half, wmma::col_major> bf;
            wmma::load_matrix_sync(af, x_h + ch*64 + ks*16, XLD);
            wmma::load_matrix_sync(bf, Wc + wid*16*WLD + ks*16, WLD);
            wmma::mma_sync(acc, af, bf, acc);
        }
    }

    wmma::store_matrix_sync(a_f + wid*16, acc, ALD, wmma::mem_row_major);
    __syncthreads();
    #pragma unroll
    for (int i = 0; i < 8; i++) {
        int idx = i*256 + t;
        int b   = idx >> 7;
        int c   = idx & 127;
        out_pv[(size_t)b*VOC + vblk + c] = a_f[b*ALD + c] + W1b[vblk + c];
    }
}

// ================= launch =================
extern "C" void kernel_launch(void* const* d_in, const int* in_sizes, int n_in,
                              void* d_out, int out_size)
{
    const int*   dec       = (const int*)  d_in[0];
    const int*   story     = (const int*)  d_in[1];
    const float* hidden    = (const float*)d_in[2];
    const int*   kb_values = (const int*)  d_in[3];
    const int*   kb_types  = (const int*)  d_in[4];
    const float* C     = (const float*)d_in[7];
    const float* T_emb = (const float*)d_in[8];
    const float* Wq    = (const float*)d_in[9];
    const float* Wk    = (const float*)d_in[10];
    const float* Wv    = (const float*)d_in[11];
    const float* W1w   = (const float*)d_in[12];
    const float* W1b   = (const float*)d_in[13];
    const float* W_ih  = (const float*)d_in[14];
    const float* W_hh  = (const float*)d_in[15];
    const float* b_ih  = (const float*)d_in[16];
    const float* b_hh  = (const float*)d_in[17];

    float* out   = (float*)d_out;
    float* p_ptr = out;
    float* p_voc = out + B*MM;
    float* h_out = out + B*MM + (size_t)B*VOC;

    static int smem_set = 0;
    if (!smem_set) {
        cudaFuncSetAttribute(K5, cudaFuncAttributeMaxDynamicSharedMemorySize, K5_SMEM);
        smem_set = 1;
    }

    K0<<<VOC*DIM/4/256, 256>>>(C);
    K1<<<K1_ROOTS + K1_STORY + K1_GEMV, 256>>>(
        kb_values, kb_types, C, T_emb, story, dec, hidden,
        W_ih, W_hh, Wq, b_ih, b_hh);
    K234<<<B + K234_CONV, 1024>>>(Wk, hidden, Wv, W1w, h_out, p_ptr);
    K5<<<VOC/TV, 256, K5_SMEM>>>(W1b, p_voc);
}